// round 4
// baseline (speedup 1.0000x reference)
#include <cuda_runtime.h>
#include <cuda_bf16.h>
#include <cstdint>

// ============================================================================
// RelationEmbeddingUpdater: out = where(type==1, emb @ W^T + b, emb)
// tcgen05 bf16 2-way-split GEMM (3 MMA passes ~ fp32 accuracy), fp32 accum in
// TMEM. Entity rows copied exactly during the load phase.
// The tcgen05 path is gated on the sm_103a feature macro (the harness also
// runs a plain compute_103 PTX pass where 'a'-features are illegal); the
// #else branch is a correct SIMT fallback.
// ============================================================================

#define D_DIM 256
#define TILE_M 128

// ---------------- smem layout (dynamic) ----------------
#define SMEM_TMEM_PTR 0
#define SMEM_MBAR     16            // 4 mbarriers x 8B
#define SMEM_BIAS     64            // 256 floats
#define SMEM_TMASK    1088          // 128 ints
#define SMEM_A        2048          // 2 bufs x (hi 16KB + lo 16KB) = 64KB
#define SMEM_A_BUFSTRIDE 32768
#define SMEM_A_LO_OFF    16384
#define SMEM_W        67584         // 2 bufs x (hi 32KB + lo 32KB) = 128KB
#define SMEM_W_BUFSTRIDE 65536
#define SMEM_W_LO_OFF    32768
#define SMEM_BYTES    198656

// idesc kind::f16: dtype=F32, atype=BF16, btype=BF16, N=256, M=128, cg1
#define MMA_IDESC 0x8400490u

// Pre-split W, laid out chunk-major in MMA-ready tiles:
// bf16 index = (k/64)*(256*64) + j*64 + (k%64)   (j = N row, k = K col)
__device__ __align__(16) __nv_bfloat16 g_Whi[D_DIM * D_DIM];
__device__ __align__(16) __nv_bfloat16 g_Wlo[D_DIM * D_DIM];

// node_type dtype flag: 1 if int64, 0 if int32 (JAX may demote int64->int32)
__device__ int g_is64;

// Feature gate: 'a'-suffix arch features (tcgen05 etc.) only exist in the
// arch-specific compilation pass.
#if defined(__CUDA_ARCH_FEAT_SM103_ALL) || defined(__CUDA_ARCH_FEAT_SM100_ALL) || defined(__CUDA_ARCH_FEAT_SM101_ALL)
#define HAS_TCGEN05 1
#else
#define HAS_TCGEN05 0
#endif

// ---------------- inline PTX helpers (only referenced in tcgen05 path) -----
static __device__ __forceinline__ uint32_t smem_u32(const void* p) {
    uint32_t a;
    asm("{ .reg .u64 t; cvta.to.shared.u64 t, %1; cvt.u32.u64 %0, t; }"
        : "=r"(a) : "l"(p));
    return a;
}
static __device__ __forceinline__ uint32_t elect_one() {
    uint32_t p;
    asm volatile("{ .reg .pred p; elect.sync _|p, 0xFFFFFFFF; selp.b32 %0, 1, 0, p; }"
                 : "=r"(p));
    return p;
}
#define SW128(o) ((o) ^ (((o) >> 3) & 0x70))

static constexpr uint64_t SMEM_DESC_BASE_SW128 =
    (uint64_t(2) << 61) | (uint64_t(1) << 46) | (uint64_t(64) << 32) | (uint64_t(1) << 16);
#define MAKE_SMEM_DESC(base_addr) \
    (SMEM_DESC_BASE_SW128 | ((uint64_t)((base_addr) >> 4) & 0x3FFF))

#define TCGEN05_ALLOC(smem_addr, nCols) \
    asm volatile("tcgen05.alloc.cta_group::1.sync.aligned.shared::cta.b32 [%0], %1;" \
        :: "r"((uint32_t)(smem_addr)), "r"((uint32_t)(nCols)) : "memory")
#define TCGEN05_DEALLOC(tmem_addr, nCols) \
    asm volatile("tcgen05.dealloc.cta_group::1.sync.aligned.b32 %0, %1;" \
        :: "r"(tmem_addr), "r"((uint32_t)(nCols)))
#define TCGEN05_RELINQUISH() \
    asm volatile("tcgen05.relinquish_alloc_permit.cta_group::1.sync.aligned;")
#define TCGEN05_COMMIT(mbar) \
    asm volatile("tcgen05.commit.cta_group::1.mbarrier::arrive::one.shared::cluster.b64 [%0];" \
        :: "r"((uint32_t)(mbar)) : "memory")
#define TCGEN05_WAIT_LD() asm volatile("tcgen05.wait::ld.sync.aligned;" ::: "memory")
#define TCGEN05_FENCE_AFTER() asm volatile("tcgen05.fence::after_thread_sync;" ::: "memory")
#define FENCE_PROXY_ASYNC_SHARED_CTA() \
    asm volatile("fence.proxy.async.shared::cta;" ::: "memory")
#define MBARRIER_INIT(mbar, count) \
    asm volatile("mbarrier.init.shared.b64 [%0], %1;" \
        :: "r"((uint32_t)(mbar)), "r"((uint32_t)(count)) : "memory")

#define MBARRIER_WAIT_PARITY(mbar_smem_addr, phase_parity) do { \
    uint32_t _mbar = (uint32_t)(mbar_smem_addr); \
    uint32_t _parity = (uint32_t)(phase_parity); \
    uint32_t _done; \
    asm volatile( \
        "{\n\t.reg .pred p;\n\t" \
        "mbarrier.try_wait.parity.acquire.cta.shared::cta.b64 p, [%1], %2;\n\t" \
        "selp.b32 %0, 1, 0, p;\n\t}" \
        : "=r"(_done) : "r"(_mbar), "r"(_parity) : "memory"); \
    if (!_done) { \
        asm volatile( \
            "{\n\t.reg .pred P1;\n\t" \
            "WAIT_LOOP_%=:\n\t" \
            "mbarrier.try_wait.parity.acquire.cta.shared::cta.b64 P1, [%0], %1, 0x989680;\n\t" \
            "@P1 bra.uni WAIT_DONE_%=;\n\t" \
            "bra.uni WAIT_LOOP_%=;\n\t" \
            "WAIT_DONE_%=:\n\t}" \
            :: "r"(_mbar), "r"(_parity) : "memory"); \
    } \
} while(0)

#define TCGEN05_LD_32X32B_X32(r, tmem_addr) \
    asm volatile( \
        "tcgen05.ld.sync.aligned.32x32b.x32.b32 " \
        "{%0, %1, %2, %3, %4, %5, %6, %7, " \
        " %8, %9, %10, %11, %12, %13, %14, %15, " \
        " %16, %17, %18, %19, %20, %21, %22, %23, " \
        " %24, %25, %26, %27, %28, %29, %30, %31}, [%32];" \
        : "=r"((r)[0]),  "=r"((r)[1]),  "=r"((r)[2]),  "=r"((r)[3]), \
          "=r"((r)[4]),  "=r"((r)[5]),  "=r"((r)[6]),  "=r"((r)[7]), \
          "=r"((r)[8]),  "=r"((r)[9]),  "=r"((r)[10]), "=r"((r)[11]), \
          "=r"((r)[12]), "=r"((r)[13]), "=r"((r)[14]), "=r"((r)[15]), \
          "=r"((r)[16]), "=r"((r)[17]), "=r"((r)[18]), "=r"((r)[19]), \
          "=r"((r)[20]), "=r"((r)[21]), "=r"((r)[22]), "=r"((r)[23]), \
          "=r"((r)[24]), "=r"((r)[25]), "=r"((r)[26]), "=r"((r)[27]), \
          "=r"((r)[28]), "=r"((r)[29]), "=r"((r)[30]), "=r"((r)[31]) \
        : "r"(tmem_addr))

#if HAS_TCGEN05
// SS-mode bf16 MMA, cta_group::1, fp32 accumulate in TMEM
static __device__ __forceinline__ void mma_bf16_ss(uint32_t d_tmem, uint64_t a_desc,
                                                   uint64_t b_desc, uint32_t enable) {
    asm volatile(
        "{\n\t"
        ".reg .pred p;\n\t"
        "setp.ne.u32 p, %5, 0;\n\t"
        "tcgen05.mma.cta_group::1.kind::f16 [%0], %1, %2, %3, {%4, %4, %4, %4}, p;\n\t"
        "}"
        :: "r"(d_tmem), "l"(a_desc), "l"(b_desc), "r"(MMA_IDESC), "r"(0u), "r"(enable)
        : "memory");
}
#endif

// ---------------- per-row type fetch, dtype-flexible ----------------
static __device__ __forceinline__ int load_type(const void* ntype, long long r, int is64) {
    if (is64) return (int)((const long long*)ntype)[r];
    return ((const int*)ntype)[r];
}

// ============================================================================
// Kernel 0: detect node_type dtype (int64 vs int32).
// int64 LE values 0/1 -> every odd 32-bit word is 0. For int32 random 0/1
// data, P(first 2048 odd words all zero) ~ 2^-2048.
// ============================================================================
__global__ void relemb_detect_kernel(const unsigned int* __restrict__ t) {
    __shared__ int found;
    if (threadIdx.x == 0) found = 0;
    __syncthreads();
    for (int i = threadIdx.x; i < 4096; i += blockDim.x)
        if ((i & 1) && t[i] != 0u) found = 1;
    __syncthreads();
    if (threadIdx.x == 0) g_is64 = found ? 0 : 1;
}

// ============================================================================
// Kernel 1: split W (fp32 -> bf16 hi + lo residual) into MMA-ready layout
// ============================================================================
__global__ void relemb_wsplit_kernel(const float* __restrict__ W) {
    int idx = blockIdx.x * 256 + threadIdx.x;     // grid 256x256 = 65536
    float x = W[idx];
    __nv_bfloat16 hi = __float2bfloat16(x);
    __nv_bfloat16 lo = __float2bfloat16(x - __bfloat162float(hi));
    int j = idx >> 8;
    int k = idx & 255;
    int dst = ((k >> 6) << 14) + (j << 6) + (k & 63);
    g_Whi[dst] = hi;
    g_Wlo[dst] = lo;
}

// ============================================================================
// Kernel 2: per-128-row-tile GEMM + select
// ============================================================================
__global__ __launch_bounds__(256, 1) void relemb_gemm_kernel(
    const float* __restrict__ emb,
    const void*  __restrict__ ntype,
    const float* __restrict__ W,      // fp32 W (used by fallback path only)
    const float* __restrict__ bias,
    float* __restrict__ out,
    int nrows)
{
#if HAS_TCGEN05
    // ======================= tcgen05 path =======================
    extern __shared__ char smem[];
    const uint32_t smem_base = smem_u32(smem);
    const int tid = threadIdx.x;
    const int wid = tid >> 5;
    const int lid = tid & 31;
    const long long tile_base = (long long)blockIdx.x * TILE_M;
    const int is64 = g_is64;

    // ---------------- prologue ----------------
    if (tid == 0) {
        #pragma unroll
        for (int c = 0; c < 4; c++) MBARRIER_INIT(smem_base + SMEM_MBAR + c * 8, 1);
    }
    if (wid == 0) {
        TCGEN05_ALLOC(smem_base + SMEM_TMEM_PTR, 256);
    }
    *(float*)(smem + SMEM_BIAS + tid * 4) = bias[tid];
    if (tid < TILE_M) {
        long long rg = tile_base + tid;
        int t = (rg < nrows) ? load_type(ntype, rg, is64) : 0;
        *(int*)(smem + SMEM_TMASK + tid * 4) = t;
    }
    __syncthreads();

    uint32_t tmem;
    asm volatile("ld.shared.b32 %0, [%1];" : "=r"(tmem) : "r"(smem_base + SMEM_TMEM_PTR));
    const int* tmask = (const int*)(smem + SMEM_TMASK);

    // ---------------- K loop: 4 chunks of 64, double buffered ----------------
    #pragma unroll 1
    for (int c = 0; c < 4; c++) {
        const int buf = c & 1;
        if (c >= 2) MBARRIER_WAIT_PARITY(smem_base + SMEM_MBAR + (c - 2) * 8, 0);

        const int aHiOff = SMEM_A + buf * SMEM_A_BUFSTRIDE;
        const int aLoOff = aHiOff + SMEM_A_LO_OFF;
        const int wHiOff = SMEM_W + buf * SMEM_W_BUFSTRIDE;
        const int wLoOff = wHiOff + SMEM_W_LO_OFF;

        // --- stage A chunk (fp32 load -> bf16 hi/lo split) + entity copy-out ---
        #pragma unroll
        for (int i = 0; i < 8; i++) {
            int u = tid + i * 256;              // 0..2047 float4 units
            int row = u >> 4;                   // 0..127
            int c4 = u & 15;                    // float4 within 64-col chunk
            long long rg = tile_base + row;
            float4 v = make_float4(0.f, 0.f, 0.f, 0.f);
            bool valid = (rg < nrows);
            if (valid) v = *(const float4*)(emb + rg * D_DIM + c * 64 + c4 * 4);

            __nv_bfloat16 h0 = __float2bfloat16(v.x);
            __nv_bfloat16 h1 = __float2bfloat16(v.y);
            __nv_bfloat16 h2 = __float2bfloat16(v.z);
            __nv_bfloat16 h3 = __float2bfloat16(v.w);
            __nv_bfloat16 l0 = __float2bfloat16(v.x - __bfloat162float(h0));
            __nv_bfloat16 l1 = __float2bfloat16(v.y - __bfloat162float(h1));
            __nv_bfloat16 l2 = __float2bfloat16(v.z - __bfloat162float(h2));
            __nv_bfloat16 l3 = __float2bfloat16(v.w - __bfloat162float(h3));
            uint32_t hi01 = ((uint32_t)__bfloat16_as_ushort(h1) << 16) | __bfloat16_as_ushort(h0);
            uint32_t hi23 = ((uint32_t)__bfloat16_as_ushort(h3) << 16) | __bfloat16_as_ushort(h2);
            uint32_t lo01 = ((uint32_t)__bfloat16_as_ushort(l1) << 16) | __bfloat16_as_ushort(l0);
            uint32_t lo23 = ((uint32_t)__bfloat16_as_ushort(l3) << 16) | __bfloat16_as_ushort(l2);

            uint32_t bo = (uint32_t)(row * 128 + c4 * 8);
            uint32_t sw = SW128(bo);
            *(uint2*)(smem + aHiOff + sw) = make_uint2(hi01, hi23);
            *(uint2*)(smem + aLoOff + sw) = make_uint2(lo01, lo23);

            // entity rows: exact fp32 passthrough, written here (coalesced)
            if (valid && tmask[row] == 0)
                *(float4*)(out + rg * D_DIM + c * 64 + c4 * 4) = v;
        }

        // --- stage W chunk (pre-split bf16, pure 16B copy with swizzle) ---
        {
            const uint4* whsrc = (const uint4*)g_Whi + c * 2048;
            const uint4* wlsrc = (const uint4*)g_Wlo + c * 2048;
            #pragma unroll
            for (int i = 0; i < 8; i++) {
                int u = tid + i * 256;          // 0..2047 16B units
                uint32_t sw = SW128((uint32_t)(u * 16));
                *(uint4*)(smem + wHiOff + sw) = whsrc[u];
                *(uint4*)(smem + wLoOff + sw) = wlsrc[u];
            }
        }

        FENCE_PROXY_ASYNC_SHARED_CTA();
        __syncthreads();

        // --- issue 12 MMAs for this chunk (hi*hi + hi*lo + lo*hi), commit ---
        if (wid == 0) {
            if (elect_one()) {
                uint64_t aHi = MAKE_SMEM_DESC(smem_base + aHiOff);
                uint64_t aLo = MAKE_SMEM_DESC(smem_base + aLoOff);
                uint64_t bHi = MAKE_SMEM_DESC(smem_base + wHiOff);
                uint64_t bLo = MAKE_SMEM_DESC(smem_base + wLoOff);
                uint32_t acc = (c != 0) ? 1u : 0u;
                #pragma unroll
                for (int s = 0; s < 4; s++) {
                    mma_bf16_ss(tmem, aHi + 2 * s, bHi + 2 * s, acc);
                    acc = 1u;
                }
                #pragma unroll
                for (int s = 0; s < 4; s++)
                    mma_bf16_ss(tmem, aHi + 2 * s, bLo + 2 * s, 1u);
                #pragma unroll
                for (int s = 0; s < 4; s++)
                    mma_bf16_ss(tmem, aLo + 2 * s, bHi + 2 * s, 1u);
                TCGEN05_COMMIT(smem_base + SMEM_MBAR + c * 8);
            }
        }
    }

    // ---------------- wait for all MMAs ----------------
    MBARRIER_WAIT_PARITY(smem_base + SMEM_MBAR + 2 * 8, 0);
    MBARRIER_WAIT_PARITY(smem_base + SMEM_MBAR + 3 * 8, 0);
    TCGEN05_FENCE_AFTER();

    // ---------------- epilogue: relation rows = D + b ----------------
    {
        int sub = wid & 3;
        int row = sub * 32 + lid;
        long long rg = tile_base + row;
        int cb0 = (wid >> 2) * 128;             // warps 0-3: cols 0-127; 4-7: 128-255
        bool rel = (rg < nrows) && (tmask[row] == 1);
        const float* sb = (const float*)(smem + SMEM_BIAS);

        #pragma unroll
        for (int cb = 0; cb < 128; cb += 32) {
            int col0 = cb0 + cb;
            uint32_t dreg[32];
            TCGEN05_LD_32X32B_X32(dreg, tmem + (uint32_t)col0);
            TCGEN05_WAIT_LD();
            if (rel) {
                #pragma unroll
                for (int i = 0; i < 8; i++) {
                    float4 v;
                    v.x = __uint_as_float(dreg[4 * i + 0]) + sb[col0 + 4 * i + 0];
                    v.y = __uint_as_float(dreg[4 * i + 1]) + sb[col0 + 4 * i + 1];
                    v.z = __uint_as_float(dreg[4 * i + 2]) + sb[col0 + 4 * i + 2];
                    v.w = __uint_as_float(dreg[4 * i + 3]) + sb[col0 + 4 * i + 3];
                    *(float4*)(out + rg * D_DIM + col0 + 4 * i) = v;
                }
            }
        }
    }

    __syncthreads();
    if (wid == 0) {
        TCGEN05_RELINQUISH();
        TCGEN05_DEALLOC(tmem, 256);
    }
#else
    // ======================= SIMT fallback (plain compute_103 pass) ========
    extern __shared__ char smem[];
    float* se = (float*)smem;                          // 128 x 256 f32 tile
    int* sm_mask = (int*)(smem + TILE_M * D_DIM * 4);  // 128 ints
    const int tid = threadIdx.x;
    const long long tile_base = (long long)blockIdx.x * TILE_M;
    const int is64 = g_is64;

    if (tid < TILE_M) {
        long long rg = tile_base + tid;
        sm_mask[tid] = (rg < nrows) ? load_type(ntype, rg, is64) : 0;
    }
    for (int i = tid; i < TILE_M * D_DIM; i += 256) {
        int r = i >> 8;
        long long rg = tile_base + r;
        se[i] = (rg < nrows) ? emb[rg * D_DIM + (i & 255)] : 0.f;
    }
    __syncthreads();

    const float bc = bias[tid];
    const float* wr = W + (long long)tid * D_DIM;   // W row for output col=tid
    for (int r = 0; r < TILE_M; r++) {
        long long rg = tile_base + r;
        if (rg >= nrows) break;
        if (sm_mask[r] == 1) {
            const float* er = se + r * D_DIM;
            float acc = 0.f;
            #pragma unroll 8
            for (int k = 0; k < D_DIM; k++) acc = fmaf(er[k], wr[k], acc);
            out[rg * D_DIM + tid] = acc + bc;
        } else {
            out[rg * D_DIM + tid] = se[r * D_DIM + tid];
        }
    }
#endif
}

// ============================================================================
// launch
// ============================================================================
extern "C" void kernel_launch(void* const* d_in, const int* in_sizes, int n_in,
                              void* d_out, int out_size) {
    const float* emb   = (const float*)d_in[0];
    const void*  ntype = d_in[1];
    const float* W     = (const float*)d_in[2];
    const float* b     = (const float*)d_in[3];
    float*       out   = (float*)d_out;
    const int nrows = in_sizes[1];              // node_type element count = N

    relemb_detect_kernel<<<1, 256>>>((const unsigned int*)ntype);
    relemb_wsplit_kernel<<<256, 256>>>(W);

    cudaFuncSetAttribute(relemb_gemm_kernel,
                         cudaFuncAttributeMaxDynamicSharedMemorySize, SMEM_BYTES);
    int tiles = (nrows + TILE_M - 1) / TILE_M;
    relemb_gemm_kernel<<<tiles, 256, SMEM_BYTES>>>(emb, ntype, W, b, out, nrows);
}